// round 5
// baseline (speedup 1.0000x reference)
#include <cuda_runtime.h>
#include <cuda_bf16.h>
#include <math.h>

#define BINS  10
#define BLOCK 256
#define GRID  1184   // 148 SMs * 8

// Per-block partials {sum,cnt}, bin-major for coalesced last-block reads.
// Written unconditionally every launch -> no zeroing kernel needed.
__device__ float2 g_part[BINS * GRID];
__device__ unsigned int g_ticket;   // zero at load; last block resets each launch

__device__ __forceinline__ void process_elem(float p, float t, float w,
                                             float2* __restrict__ hist) {
    // t in {0,1}: q = p*(1-2t); then |sigmoid(p)-t| = sigmoid(q), bce = softplus(q)
    float q  = fmaf(p, -2.0f * t, p);
    float aq = fabsf(q);
    float e  = __expf(-aq);                 // exp(-|q|) in (0,1]
    float r;                                 // approx 1/(1+e), only for binning
    asm("rcp.approx.f32 %0, %1;" : "=f"(r) : "f"(1.0f + e));
    float g  = (q >= 0.0f) ? r : e * r;     // sigmoid(q)
    int bin  = (int)(g * 10.0f);
    bin = bin > (BINS - 1) ? (BINS - 1) : bin;
    // bce independent of approx r: max(q,0) + log(1+e)
    float bce = fmaxf(q, 0.0f) + __logf(1.0f + e);
    float2 a = hist[bin * BLOCK];           // LDS.64, conflict-free ([bin][tid])
    a.x += bce * w;                         // w in {0,1}
    a.y += w;
    hist[bin * BLOCK] = a;                  // STS.64
}

__global__ void __launch_bounds__(BLOCK)
ghm_main(const float* __restrict__ pred,
         const float* __restrict__ target,
         const float* __restrict__ lw,
         int n, float* __restrict__ out) {
    // Per-thread private histogram: [bin][tid] float2 -> conflict-free 64-bit access.
    __shared__ float2 s_hist[BINS * BLOCK];

    const int tid = threadIdx.x;
    float2* __restrict__ hist = s_hist + tid;   // per-thread column base
#pragma unroll
    for (int b = 0; b < BINS; b++)
        hist[b * BLOCK] = make_float2(0.0f, 0.0f);

    const int n4 = n >> 2;
    const float4* __restrict__ p4 = (const float4*)pred;
    const float4* __restrict__ t4 = (const float4*)target;
    const float4* __restrict__ w4 = (const float4*)lw;

    const int stride = GRID * BLOCK;
    int i = blockIdx.x * BLOCK + tid;

    if (i < n4) {
        // Software pipeline: loads for iter k+1 issue before processing iter k,
        // so DRAM latency overlaps the smem-RMW compute chain.
        float4 pa = p4[i];
        float4 ta = t4[i];
        float4 wa = w4[i];
        int inext = i + stride;
        while (inext < n4) {
            float4 pb = p4[inext];
            float4 tb = t4[inext];
            float4 wb = w4[inext];
            process_elem(pa.x, ta.x, wa.x, hist);
            process_elem(pa.y, ta.y, wa.y, hist);
            process_elem(pa.z, ta.z, wa.z, hist);
            process_elem(pa.w, ta.w, wa.w, hist);
            pa = pb; ta = tb; wa = wb;
            inext += stride;
        }
        process_elem(pa.x, ta.x, wa.x, hist);
        process_elem(pa.y, ta.y, wa.y, hist);
        process_elem(pa.z, ta.z, wa.z, hist);
        process_elem(pa.w, ta.w, wa.w, hist);
    }
    // Scalar tail (n not multiple of 4) — block 0 only.
    if (blockIdx.x == 0) {
        for (int j = (n4 << 2) + tid; j < n; j += BLOCK)
            process_elem(pred[j], target[j], lw[j], hist);
    }

    __syncthreads();
    // Tree-reduce each bin's 256 partials.
    for (int s = BLOCK / 2; s > 0; s >>= 1) {
        if (tid < s) {
#pragma unroll
            for (int b = 0; b < BINS; b++) {
                float2 x = s_hist[b * BLOCK + tid];
                float2 y = s_hist[b * BLOCK + tid + s];
                s_hist[b * BLOCK + tid] = make_float2(x.x + y.x, x.y + y.y);
            }
        }
        __syncthreads();
    }
    if (tid < BINS) {
        g_part[tid * GRID + blockIdx.x] = s_hist[tid * BLOCK];  // cnt <= ~28K, fp32-exact
        __threadfence();   // only the 10 writer threads fence (release)
    }
    __syncthreads();

    // ---- last-block finalization ----
    __shared__ bool s_last;
    if (tid == 0) {
        unsigned int t = atomicAdd(&g_ticket, 1u);
        s_last = (t == GRID - 1u);
    }
    __syncthreads();
    if (!s_last) return;

    __shared__ double r_sum[BINS * (BLOCK / 32)];
    __shared__ double r_cnt[BINS * (BLOCK / 32)];
    const int lane = tid & 31, wid = tid >> 5;
    const int NW = BLOCK / 32;

#pragma unroll
    for (int b = 0; b < BINS; b++) {
        float fs = 0.0f, fc = 0.0f;
        for (int j = tid; j < GRID; j += BLOCK) {
            double raw = __ldcg((const double*)&g_part[b * GRID + j]);  // coalesced, bypass stale L1
            float2 v = *(float2*)&raw;
            fs += v.x;
            fc += v.y;   // sum of <=5 block-counts, each <2^18 -> exact
        }
        double ds = (double)fs, dc = (double)fc;
#pragma unroll
        for (int o = 16; o > 0; o >>= 1) {
            ds += __shfl_down_sync(0xFFFFFFFFu, ds, o);
            dc += __shfl_down_sync(0xFFFFFFFFu, dc, o);
        }
        if (lane == 0) { r_sum[b * NW + wid] = ds; r_cnt[b * NW + wid] = dc; }
    }
    __syncthreads();

    if (tid == 0) {
        double acc = 0.0;
        int ne = 0;
#pragma unroll
        for (int b = 0; b < BINS; b++) {
            double s = 0.0, c = 0.0;
#pragma unroll
            for (int w = 0; w < NW; w++) { s += r_sum[b * NW + w]; c += r_cnt[b * NW + w]; }
            if (c > 0.0) { acc += s / c; ne++; }
        }
        float loss = (ne > 0) ? (float)(acc / (double)ne) : 0.0f;
        out[0] = loss * 1.0f;   // LOSS_WEIGHT
        g_ticket = 0u;          // reset for next graph replay
    }
}

extern "C" void kernel_launch(void* const* d_in, const int* in_sizes, int n_in,
                              void* d_out, int out_size) {
    const float* pred   = (const float*)d_in[0];
    const float* target = (const float*)d_in[1];
    const float* lw     = (const float*)d_in[2];
    float* out = (float*)d_out;
    int n = in_sizes[0];

    ghm_main<<<GRID, BLOCK>>>(pred, target, lw, n, out);
}